// round 15
// baseline (speedup 1.0000x reference)
#include <cuda_runtime.h>
#include <cuda_fp16.h>
#include <cstdint>

#define NMAX 100000
#define EMAX 1600000
#define HDIM 128
#define WARPS_PER_BLK 8

// Scratch (static device globals — no runtime allocation, zero-initialized;
// k_agg restores the zero state for g_cnt/g_total after each use).
__device__                int    g_total;                       // bucket cursor base
__device__ __align__(128) int    g_cnt [NMAX];                  // incoming-edge count
__device__ __align__(128) int    g_off [NMAX];                  // bucket offsets
__device__ __align__(128) int    g_cur [NMAX];                  // bucket cursors
__device__ __align__(128) float  g_dinv[NMAX];                  // 1/sqrt(deg)
__device__ __align__(128) float2 g_edge[EMAX];                  // {src bits, norm} dst-bucketed
__device__ __align__(256) __half g_h16 [(size_t)NMAX * HDIM];   // x @ W_conv (fp16)
__device__ __align__(256) float  g_hs  [(size_t)NMAX * HDIM];   // x @ W_skip (fp32)

// Block-local dtype detect: int64 little-endian indices < 2^32 have zero
// high words across the first 64 entries.
__device__ __forceinline__ int detect_is64(const int* __restrict__ ei32) {
    int ornz = 0;
#pragma unroll
    for (int k = 0; k < 64; k++) ornz |= ei32[2 * k + 1];
    return (ornz == 0) ? 1 : 0;
}

__device__ __forceinline__ void decode_edge(const void* __restrict__ ei, int E,
                                            int n, int e, int is64,
                                            int& src, int& dst) {
    if (is64) {
        src = (int)((const long long*)ei)[e];
        dst = (int)((const long long*)ei)[(size_t)E + e];
    } else {
        src = ((const int*)ei)[e];
        dst = ((const int*)ei)[(size_t)E + e];
    }
    src = min(max(src, 0), n - 1);
    dst = min(max(dst, 0), n - 1);
}

// ---------------------------------------------------------------- degree histogram
__global__ void k_degree(const void* __restrict__ ei, int E, int n) {
    __shared__ int s_is64;
    if (threadIdx.x == 0) s_is64 = detect_is64((const int*)ei);
    __syncthreads();
    int is64 = s_is64;
    int e = blockIdx.x * blockDim.x + threadIdx.x;
    if (e >= E) return;
    int src, dst;
    decode_edge(ei, E, n, e, is64, src, dst);
    atomicAdd(&g_cnt[dst], 1);
}

// ---------------------------------------------------------------- offsets (scan-free) + dinv
__global__ void k_offsets(int n) {
    __shared__ int wsum[8];
    __shared__ int bbase;
    int i    = blockIdx.x * 256 + threadIdx.x;
    int lane = threadIdx.x & 31;
    int wid  = threadIdx.x >> 5;

    int c = (i < n) ? g_cnt[i] : 0;
    int v = c;
#pragma unroll
    for (int o = 1; o < 32; o <<= 1) {
        int t = __shfl_up_sync(0xffffffffu, v, o);
        if (lane >= o) v += t;
    }
    if (lane == 31) wsum[wid] = v;
    __syncthreads();
    if (threadIdx.x == 0) {
        int run = 0;
#pragma unroll
        for (int w = 0; w < 8; w++) { int t = wsum[w]; wsum[w] = run; run += t; }
        bbase = atomicAdd(&g_total, run);
    }
    __syncthreads();
    if (i < n) {
        int excl = bbase + wsum[wid] + v - c;
        g_off[i] = excl;
        g_cur[i] = excl;
        g_dinv[i] = rsqrtf((float)c + 2.0f);   // improved=True: +2 self-loop
    }
}

// ---------------------------------------------------------------- bucket (counting sort by dst)
__global__ void k_bucket(const void* __restrict__ ei, int E, int n) {
    __shared__ int s_is64;
    if (threadIdx.x == 0) s_is64 = detect_is64((const int*)ei);
    __syncthreads();
    int is64 = s_is64;
    int e = blockIdx.x * blockDim.x + threadIdx.x;
    if (e >= E) return;
    int src, dst;
    decode_edge(ei, E, n, e, is64, src, dst);
    float nrm = g_dinv[src] * g_dinv[dst];
    int pos = atomicAdd(&g_cur[dst], 1);
    g_edge[pos] = make_float2(__int_as_float(src), nrm);
}

// ---------------------------------------------------------------- HMMA dual GEMM
// mma.sync m16n8k16 fp16 (base ISA). Split precision:
//   D = x_hi·W_hi + x_lo·W_hi + x_hi·W_lo   (lo·lo term ~2^-22, dropped)
#define SA_STR 40
#define SB_STR 40
#define SA_HALVES (128 * SA_STR)            // per hi/lo tile
#define SB_HALVES (256 * SB_STR)
#define SMEM_MMA ((2 * SA_HALVES + 2 * SB_HALVES) * 2)   // 61440 bytes

__device__ __forceinline__ void mma16816(float* d, const uint32_t* a,
                                         uint32_t b0, uint32_t b1) {
    asm volatile(
        "mma.sync.aligned.m16n8k16.row.col.f32.f16.f16.f32 "
        "{%0,%1,%2,%3}, {%4,%5,%6,%7}, {%8,%9}, {%0,%1,%2,%3};"
        : "+f"(d[0]), "+f"(d[1]), "+f"(d[2]), "+f"(d[3])
        : "r"(a[0]), "r"(a[1]), "r"(a[2]), "r"(a[3]), "r"(b0), "r"(b1));
}

__device__ __forceinline__ uint32_t pack_half2(float a, float b) {
    __half2 h = __floats2half2_rn(a, b);
    return *(uint32_t*)&h;
}

__global__ __launch_bounds__(512) void k_gemm_mma(const float* __restrict__ x,
                                                  const float* __restrict__ Wc,
                                                  const float* __restrict__ Ws,
                                                  int n) {
    extern __shared__ __align__(16) __half smem[];
    __half* sAhi = smem;
    __half* sAlo = sAhi + SA_HALVES;
    __half* sBhi = sAlo + SA_HALVES;
    __half* sBlo = sBhi + SB_HALVES;

    const int tid  = threadIdx.x;
    const int wid  = tid >> 5;
    const int lane = tid & 31;
    const int g    = lane >> 2;     // group id (0..7)
    const int tg   = lane & 3;      // thread in group
    const int mw   = (wid & 3) * 32;    // warp M offset (rows)
    const int nw   = (wid >> 2) * 64;   // warp N offset (cols of 256)
    const int node0 = blockIdx.x * 128;

    float d[2][8][4];
#pragma unroll
    for (int mi = 0; mi < 2; mi++)
#pragma unroll
        for (int ni = 0; ni < 8; ni++)
#pragma unroll
            for (int q = 0; q < 4; q++) d[mi][ni][q] = 0.f;

    for (int kc = 0; kc < 4; kc++) {
        // ---- load + split x chunk: 128 rows x 32 k (1024 float4, 2/thread)
#pragma unroll
        for (int i = 0; i < 2; i++) {
            int f4  = i * 512 + tid;
            int row = f4 >> 3;
            int k4  = f4 & 7;
            int node = node0 + row;
            float4 v = make_float4(0.f, 0.f, 0.f, 0.f);
            if (node < n) v = ((const float4*)x)[(size_t)node * 32 + kc * 8 + k4];
            float hx = __half2float(__float2half_rn(v.x));
            float hy = __half2float(__float2half_rn(v.y));
            float hz = __half2float(__float2half_rn(v.z));
            float hw = __half2float(__float2half_rn(v.w));
            int base = row * SA_STR + k4 * 4;
            *(uint32_t*)&sAhi[base]     = pack_half2(hx, hy);
            *(uint32_t*)&sAhi[base + 2] = pack_half2(hz, hw);
            *(uint32_t*)&sAlo[base]     = pack_half2(v.x - hx, v.y - hy);
            *(uint32_t*)&sAlo[base + 2] = pack_half2(v.z - hz, v.w - hw);
        }
        // ---- load + split W chunk: 32 k x 256 cols (8192 elems, 16/thread)
#pragma unroll
        for (int i = 0; i < 16; i++) {
            int f    = i * 512 + tid;
            int k    = f >> 8;
            int ncol = f & 255;
            int krow = kc * 32 + k;
            float v = (ncol < 128) ? Wc[krow * 128 + ncol]
                                   : Ws[krow * 128 + (ncol - 128)];
            __half hi = __float2half_rn(v);
            sBhi[ncol * SB_STR + k] = hi;
            sBlo[ncol * SB_STR + k] = __float2half_rn(v - __half2float(hi));
        }
        __syncthreads();

        // ---- 3 split passes x 2 k16 steps
#pragma unroll
        for (int p = 0; p < 3; p++) {
            const __half* A = (p == 1) ? sAlo : sAhi;
            const __half* B = (p == 2) ? sBlo : sBhi;
#pragma unroll
            for (int kk = 0; kk < 32; kk += 16) {
                uint32_t a[2][4];
#pragma unroll
                for (int mi = 0; mi < 2; mi++) {
                    int r0 = (mw + mi * 16 + g) * SA_STR + kk + tg * 2;
                    int r1 = r0 + 8 * SA_STR;
                    a[mi][0] = *(const uint32_t*)(A + r0);
                    a[mi][1] = *(const uint32_t*)(A + r1);
                    a[mi][2] = *(const uint32_t*)(A + r0 + 8);
                    a[mi][3] = *(const uint32_t*)(A + r1 + 8);
                }
#pragma unroll
                for (int ni = 0; ni < 8; ni++) {
                    int nb = (nw + ni * 8 + g) * SB_STR + kk + tg * 2;
                    uint32_t b0 = *(const uint32_t*)(B + nb);
                    uint32_t b1 = *(const uint32_t*)(B + nb + 8);
                    mma16816(d[0][ni], a[0], b0, b1);
                    mma16816(d[1][ni], a[1], b0, b1);
                }
            }
        }
        __syncthreads();
    }

    // ---- epilogue: conv half -> fp16 only; skip half -> fp32
#pragma unroll
    for (int mi = 0; mi < 2; mi++) {
#pragma unroll
        for (int hr = 0; hr < 2; hr++) {
            int node = node0 + mw + mi * 16 + g + hr * 8;
            if (node >= n) continue;
#pragma unroll
            for (int ni = 0; ni < 8; ni++) {
                int col = nw + ni * 8 + tg * 2;
                float v0 = d[mi][ni][hr * 2 + 0];
                float v1 = d[mi][ni][hr * 2 + 1];
                if (col < 128) {
                    *(uint32_t*)&g_h16[(size_t)node * HDIM + col] = pack_half2(v0, v1);
                } else {
                    *(float2*)&g_hs[(size_t)node * HDIM + (col - 128)] =
                        make_float2(v0, v1);
                }
            }
        }
    }
}

// ---------------------------------------------------------------- fused aggregation + epilogue
// One warp per node. Decoupled gathers: per 16-edge wave, ONE coalesced 64B
// meta load, then 8 cp.async instructions stage all 16 src rows (256 B each)
// into shared — no register dependency, one wait per wave. Lane l owns
// features [4l, 4l+4). Also resets g_cnt/g_total for the next call.
__global__ __launch_bounds__(256) void k_agg(const float* __restrict__ bconv,
                                             const float* __restrict__ bskip,
                                             float* __restrict__ out, int n) {
    __shared__ __align__(16) char sbuf[WARPS_PER_BLK][16 * 256];   // 32 KB
    const int tid  = threadIdx.x;
    const int lane = tid & 31;
    const int w    = tid >> 5;
    const int node = blockIdx.x * WARPS_PER_BLK + w;

    if (blockIdx.x == 0 && tid == 0) g_total = 0;
    if (node >= n) return;

    const int beg = g_off[node];
    const int cnt = g_cnt[node];
    const int end = beg + cnt;
    if (lane == 0) g_cnt[node] = 0;    // restore zero state for next call

    const int l16   = lane & 15;
    const int rhalf = lane >> 4;       // 0 or 1
    char* mybuf = sbuf[w];
    uint32_t sbase;
    asm("{ .reg .u64 t; cvta.to.shared.u64 t, %1; cvt.u32.u64 %0, t; }"
        : "=r"(sbase) : "l"(mybuf));

    float4 acc = make_float4(0.f, 0.f, 0.f, 0.f);
    for (int base = beg; base < end; base += 16) {
        // lanes 0..15 carry metas for edges base..base+15 (clamped)
        float2 meta = g_edge[min(base + l16, end - 1)];
        int msrc = __float_as_int(meta.x);

        // stage 16 rows: instr k moves rows {2k, 2k+1}; lane l -> row 2k+(l>>4),
        // bytes [(l&15)*16, +16). Rows past end replicate the last edge (norm=0 later).
#pragma unroll
        for (int k = 0; k < 8; k++) {
            int r = 2 * k + rhalf;
            int srcr = __shfl_sync(0xffffffffu, msrc, r);
            const char* gp = (const char*)(g_h16 + (size_t)srcr * HDIM) + l16 * 16;
            uint32_t sp = sbase + (uint32_t)(r * 256 + l16 * 16);
            asm volatile("cp.async.cg.shared.global [%0], [%1], 16;"
                         :: "r"(sp), "l"(gp) : "memory");
        }
        asm volatile("cp.async.commit_group;" ::: "memory");
        asm volatile("cp.async.wait_group 0;" ::: "memory");
        __syncwarp();

#pragma unroll
        for (int u = 0; u < 16; u++) {
            float sm = __shfl_sync(0xffffffffu, meta.y, u);
            float nm = (base + u < end) ? sm : 0.f;
            uint2 hv = *(const uint2*)(mybuf + u * 256 + lane * 8);
            float2 f01 = __half22float2(*(__half2*)&hv.x);
            float2 f23 = __half22float2(*(__half2*)&hv.y);
            acc.x += nm * f01.x;
            acc.y += nm * f01.y;
            acc.z += nm * f23.x;
            acc.w += nm * f23.y;
        }
        __syncwarp();   // before next wave overwrites the buffer
    }

    float di  = g_dinv[node];
    float swt = 2.0f * di * di;

    uint2  hh  = ((const uint2*)&g_h16[(size_t)node * HDIM])[lane];
    float2 h01 = __half22float2(*(__half2*)&hh.x);
    float2 h23 = __half22float2(*(__half2*)&hh.y);
    float4 hs4 = ((const float4*)&g_hs[(size_t)node * HDIM])[lane];
    float4 bc  = ((const float4*)bconv)[lane];
    float4 bs  = ((const float4*)bskip)[lane];

    float4 o;
    o.x = acc.x + swt * h01.x + bc.x + hs4.x + bs.x;
    o.y = acc.y + swt * h01.y + bc.y + hs4.y + bs.y;
    o.z = acc.z + swt * h23.x + bc.z + hs4.z + bs.z;
    o.w = acc.w + swt * h23.y + bc.w + hs4.w + bs.w;

    o.x = (o.x > 0.f) ? o.x : 0.1f * (__expf(o.x) - 1.0f);
    o.y = (o.y > 0.f) ? o.y : 0.1f * (__expf(o.y) - 1.0f);
    o.z = (o.z > 0.f) ? o.z : 0.1f * (__expf(o.z) - 1.0f);
    o.w = (o.w > 0.f) ? o.w : 0.1f * (__expf(o.w) - 1.0f);

    ((float4*)&out[(size_t)node * HDIM])[lane] = o;
}

// ---------------------------------------------------------------- launch
// 5 launches: gemm (s2), degree, offsets, bucket, agg.
extern "C" void kernel_launch(void* const* d_in, const int* in_sizes, int n_in,
                              void* d_out, int out_size) {
    const float* x  = (const float*)d_in[0];
    const void*  ei = d_in[1];
    const float* Wc = (const float*)d_in[2];
    const float* bc = (const float*)d_in[3];
    const float* Ws = (const float*)d_in[4];
    const float* bs = (const float*)d_in[5];
    float* out = (float*)d_out;

    const int n = in_sizes[0] / HDIM;
    const int E = in_sizes[1] / 2;

    static cudaStream_t s2 = []() {
        cudaStream_t s; cudaStreamCreateWithFlags(&s, cudaStreamNonBlocking); return s;
    }();
    static cudaEvent_t ev_fork = []() {
        cudaEvent_t e; cudaEventCreateWithFlags(&e, cudaEventDisableTiming); return e;
    }();
    static cudaEvent_t ev_gemm = []() {
        cudaEvent_t e; cudaEventCreateWithFlags(&e, cudaEventDisableTiming); return e;
    }();
    static bool attr_done = []() {
        cudaFuncSetAttribute(k_gemm_mma,
                             cudaFuncAttributeMaxDynamicSharedMemorySize, SMEM_MMA);
        return true;
    }();
    (void)attr_done;

    // Fork: GEMM on s2, concurrent with edge preprocessing on the main stream.
    cudaEventRecord(ev_fork, 0);
    cudaStreamWaitEvent(s2, ev_fork, 0);
    k_gemm_mma<<<(n + 127) / 128, 512, SMEM_MMA, s2>>>(x, Wc, Ws, n);
    cudaEventRecord(ev_gemm, s2);

    k_degree <<<(E + 255) / 256, 256>>>(ei, E, n);
    k_offsets<<<(n + 255) / 256, 256>>>(n);
    k_bucket <<<(E + 255) / 256, 256>>>(ei, E, n);

    // Join: aggregation needs both the bucketed edges and g_h16/g_hs.
    cudaStreamWaitEvent(0, ev_gemm, 0);
    k_agg<<<(n + WARPS_PER_BLK - 1) / WARPS_PER_BLK, 256>>>(bc, bs, out, n);
}

// round 16
// speedup vs baseline: 1.1673x; 1.1673x over previous
#include <cuda_runtime.h>
#include <cuda_fp16.h>
#include <cstdint>

#define NMAX 100000
#define EMAX 1600000
#define HDIM 128

// Scratch (static device globals — no runtime allocation, zero-initialized;
// k_agg restores the zero state of g_cnt/g_total after each use).
__device__                int    g_total;                       // bucket cursor base
__device__ __align__(128) int    g_cnt [NMAX];                  // incoming-edge count
__device__ __align__(128) int    g_off [NMAX];                  // bucket offsets
__device__ __align__(128) int    g_cur [NMAX];                  // bucket cursors
__device__ __align__(128) float  g_dinv[NMAX];                  // 1/sqrt(deg)
__device__ __align__(128) float2 g_edge[EMAX];                  // {src bits, norm} dst-bucketed
__device__ __align__(256) __half g_h16 [(size_t)NMAX * HDIM];   // x @ W_conv (fp16)
__device__ __align__(256) float  g_hs  [(size_t)NMAX * HDIM];   // x @ W_skip (fp32)

// Block-local dtype detect: int64 little-endian indices < 2^32 have zero
// high words across the first 64 entries.
__device__ __forceinline__ int detect_is64(const int* __restrict__ ei32) {
    int ornz = 0;
#pragma unroll
    for (int k = 0; k < 64; k++) ornz |= ei32[2 * k + 1];
    return (ornz == 0) ? 1 : 0;
}

__device__ __forceinline__ void decode_edge(const void* __restrict__ ei, int E,
                                            int n, int e, int is64,
                                            int& src, int& dst) {
    if (is64) {
        src = (int)((const long long*)ei)[e];
        dst = (int)((const long long*)ei)[(size_t)E + e];
    } else {
        src = ((const int*)ei)[e];
        dst = ((const int*)ei)[(size_t)E + e];
    }
    src = min(max(src, 0), n - 1);
    dst = min(max(dst, 0), n - 1);
}

// ---------------------------------------------------------------- degree histogram
__global__ void k_degree(const void* __restrict__ ei, int E, int n) {
    __shared__ int s_is64;
    if (threadIdx.x == 0) s_is64 = detect_is64((const int*)ei);
    __syncthreads();
    int is64 = s_is64;
    int e = blockIdx.x * blockDim.x + threadIdx.x;
    if (e >= E) return;
    int src, dst;
    decode_edge(ei, E, n, e, is64, src, dst);
    atomicAdd(&g_cnt[dst], 1);
}

// ---------------------------------------------------------------- offsets (scan-free) + dinv
__global__ void k_offsets(int n) {
    __shared__ int wsum[8];
    __shared__ int bbase;
    int i    = blockIdx.x * 256 + threadIdx.x;
    int lane = threadIdx.x & 31;
    int wid  = threadIdx.x >> 5;

    int c = (i < n) ? g_cnt[i] : 0;
    int v = c;
#pragma unroll
    for (int o = 1; o < 32; o <<= 1) {
        int t = __shfl_up_sync(0xffffffffu, v, o);
        if (lane >= o) v += t;
    }
    if (lane == 31) wsum[wid] = v;
    __syncthreads();
    if (threadIdx.x == 0) {
        int run = 0;
#pragma unroll
        for (int w = 0; w < 8; w++) { int t = wsum[w]; wsum[w] = run; run += t; }
        bbase = atomicAdd(&g_total, run);
    }
    __syncthreads();
    if (i < n) {
        int excl = bbase + wsum[wid] + v - c;
        g_off[i] = excl;
        g_cur[i] = excl;
        g_dinv[i] = rsqrtf((float)c + 2.0f);   // improved=True: +2 self-loop
    }
}

// ---------------------------------------------------------------- bucket (counting sort by dst)
__global__ void k_bucket(const void* __restrict__ ei, int E, int n) {
    __shared__ int s_is64;
    if (threadIdx.x == 0) s_is64 = detect_is64((const int*)ei);
    __syncthreads();
    int is64 = s_is64;
    int e = blockIdx.x * blockDim.x + threadIdx.x;
    if (e >= E) return;
    int src, dst;
    decode_edge(ei, E, n, e, is64, src, dst);
    float nrm = g_dinv[src] * g_dinv[dst];
    int pos = atomicAdd(&g_cur[dst], 1);
    g_edge[pos] = make_float2(__int_as_float(src), nrm);
}

// ---------------------------------------------------------------- HMMA dual GEMM
// mma.sync m16n8k16 fp16 (base ISA). Split precision:
//   D = x_hi·W_hi + x_lo·W_hi + x_hi·W_lo   (lo·lo term ~2^-22, dropped)
#define SA_STR 40
#define SB_STR 40
#define SA_HALVES (128 * SA_STR)            // per hi/lo tile
#define SB_HALVES (256 * SB_STR)
#define SMEM_MMA ((2 * SA_HALVES + 2 * SB_HALVES) * 2)   // 61440 bytes

__device__ __forceinline__ void mma16816(float* d, const uint32_t* a,
                                         uint32_t b0, uint32_t b1) {
    asm volatile(
        "mma.sync.aligned.m16n8k16.row.col.f32.f16.f16.f32 "
        "{%0,%1,%2,%3}, {%4,%5,%6,%7}, {%8,%9}, {%0,%1,%2,%3};"
        : "+f"(d[0]), "+f"(d[1]), "+f"(d[2]), "+f"(d[3])
        : "r"(a[0]), "r"(a[1]), "r"(a[2]), "r"(a[3]), "r"(b0), "r"(b1));
}

__device__ __forceinline__ uint32_t pack_half2(float a, float b) {
    __half2 h = __floats2half2_rn(a, b);
    return *(uint32_t*)&h;
}

__global__ __launch_bounds__(512) void k_gemm_mma(const float* __restrict__ x,
                                                  const float* __restrict__ Wc,
                                                  const float* __restrict__ Ws,
                                                  int n) {
    extern __shared__ __align__(16) __half smem[];
    __half* sAhi = smem;
    __half* sAlo = sAhi + SA_HALVES;
    __half* sBhi = sAlo + SA_HALVES;
    __half* sBlo = sBhi + SB_HALVES;

    const int tid  = threadIdx.x;
    const int wid  = tid >> 5;
    const int lane = tid & 31;
    const int g    = lane >> 2;     // group id (0..7)
    const int tg   = lane & 3;      // thread in group
    const int mw   = (wid & 3) * 32;    // warp M offset (rows)
    const int nw   = (wid >> 2) * 64;   // warp N offset (cols of 256)
    const int node0 = blockIdx.x * 128;

    float d[2][8][4];
#pragma unroll
    for (int mi = 0; mi < 2; mi++)
#pragma unroll
        for (int ni = 0; ni < 8; ni++)
#pragma unroll
            for (int q = 0; q < 4; q++) d[mi][ni][q] = 0.f;

    for (int kc = 0; kc < 4; kc++) {
        // ---- load + split x chunk: 128 rows x 32 k (1024 float4, 2/thread)
#pragma unroll
        for (int i = 0; i < 2; i++) {
            int f4  = i * 512 + tid;
            int row = f4 >> 3;
            int k4  = f4 & 7;
            int node = node0 + row;
            float4 v = make_float4(0.f, 0.f, 0.f, 0.f);
            if (node < n) v = ((const float4*)x)[(size_t)node * 32 + kc * 8 + k4];
            float hx = __half2float(__float2half_rn(v.x));
            float hy = __half2float(__float2half_rn(v.y));
            float hz = __half2float(__float2half_rn(v.z));
            float hw = __half2float(__float2half_rn(v.w));
            int base = row * SA_STR + k4 * 4;
            *(uint32_t*)&sAhi[base]     = pack_half2(hx, hy);
            *(uint32_t*)&sAhi[base + 2] = pack_half2(hz, hw);
            *(uint32_t*)&sAlo[base]     = pack_half2(v.x - hx, v.y - hy);
            *(uint32_t*)&sAlo[base + 2] = pack_half2(v.z - hz, v.w - hw);
        }
        // ---- load + split W chunk: 32 k x 256 cols (8192 elems, 16/thread)
#pragma unroll
        for (int i = 0; i < 16; i++) {
            int f    = i * 512 + tid;
            int k    = f >> 8;
            int ncol = f & 255;
            int krow = kc * 32 + k;
            float v = (ncol < 128) ? Wc[krow * 128 + ncol]
                                   : Ws[krow * 128 + (ncol - 128)];
            __half hi = __float2half_rn(v);
            sBhi[ncol * SB_STR + k] = hi;
            sBlo[ncol * SB_STR + k] = __float2half_rn(v - __half2float(hi));
        }
        __syncthreads();

        // ---- 3 split passes x 2 k16 steps
#pragma unroll
        for (int p = 0; p < 3; p++) {
            const __half* A = (p == 1) ? sAlo : sAhi;
            const __half* B = (p == 2) ? sBlo : sBhi;
#pragma unroll
            for (int kk = 0; kk < 32; kk += 16) {
                uint32_t a[2][4];
#pragma unroll
                for (int mi = 0; mi < 2; mi++) {
                    int r0 = (mw + mi * 16 + g) * SA_STR + kk + tg * 2;
                    int r1 = r0 + 8 * SA_STR;
                    a[mi][0] = *(const uint32_t*)(A + r0);
                    a[mi][1] = *(const uint32_t*)(A + r1);
                    a[mi][2] = *(const uint32_t*)(A + r0 + 8);
                    a[mi][3] = *(const uint32_t*)(A + r1 + 8);
                }
#pragma unroll
                for (int ni = 0; ni < 8; ni++) {
                    int nb = (nw + ni * 8 + g) * SB_STR + kk + tg * 2;
                    uint32_t b0 = *(const uint32_t*)(B + nb);
                    uint32_t b1 = *(const uint32_t*)(B + nb + 8);
                    mma16816(d[0][ni], a[0], b0, b1);
                    mma16816(d[1][ni], a[1], b0, b1);
                }
            }
        }
        __syncthreads();
    }

    // ---- epilogue: conv half -> fp16 only; skip half -> fp32
#pragma unroll
    for (int mi = 0; mi < 2; mi++) {
#pragma unroll
        for (int hr = 0; hr < 2; hr++) {
            int node = node0 + mw + mi * 16 + g + hr * 8;
            if (node >= n) continue;
#pragma unroll
            for (int ni = 0; ni < 8; ni++) {
                int col = nw + ni * 8 + tg * 2;
                float v0 = d[mi][ni][hr * 2 + 0];
                float v1 = d[mi][ni][hr * 2 + 1];
                if (col < 128) {
                    *(uint32_t*)&g_h16[(size_t)node * HDIM + col] = pack_half2(v0, v1);
                } else {
                    *(float2*)&g_hs[(size_t)node * HDIM + (col - 128)] =
                        make_float2(v0, v1);
                }
            }
        }
    }
}

// ---------------------------------------------------------------- fused aggregation + epilogue
// TWO warps per node (R13 structure) + software-pipelined metadata: batch
// k+1's meta loads issue while batch k's gathers are in flight, so the
// meta->gather chain restart is hidden after the first batch.
__global__ __launch_bounds__(256) void k_agg(const float* __restrict__ bconv,
                                             const float* __restrict__ bskip,
                                             float* __restrict__ out, int n) {
    __shared__ float4 s_part[4][32];
    const int tid  = threadIdx.x;
    const int lane = tid & 31;
    const int wid  = tid >> 5;
    const int nloc = wid >> 1;          // node slot in block (0..3)
    const int sw   = wid & 1;           // sub-warp of the pair
    const int node = blockIdx.x * 4 + nloc;
    const bool valid = (node < n);

    if (blockIdx.x == 0 && tid == 0) g_total = 0;

    int beg = 0, cnt = 0;
    if (valid) { beg = g_off[node]; cnt = g_cnt[node]; }
    const int half = cnt >> 1;
    const int jb = sw ? (beg + half) : beg;
    const int je = sw ? (beg + cnt)  : (beg + half);

    float4 acc = make_float4(0.f, 0.f, 0.f, 0.f);

    int j = jb;
    float2 e[8];
    bool have = (j + 8 <= je);
    if (have) {
#pragma unroll
        for (int u = 0; u < 8; u++) e[u] = g_edge[j + u];
    }
    while (have) {
        uint2 h[8];
#pragma unroll
        for (int u = 0; u < 8; u++)
            h[u] = ((const uint2*)&g_h16[(size_t)__float_as_int(e[u].x) * HDIM])[lane];

        // prefetch next batch's metadata while gathers are in flight
        int jn = j + 8;
        bool haveNext = (jn + 8 <= je);
        float2 en[8];
        if (haveNext) {
#pragma unroll
            for (int u = 0; u < 8; u++) en[u] = g_edge[jn + u];
        }

#pragma unroll
        for (int u = 0; u < 8; u++) {
            float2 f01 = __half22float2(*(__half2*)&h[u].x);
            float2 f23 = __half22float2(*(__half2*)&h[u].y);
            acc.x += e[u].y * f01.x;
            acc.y += e[u].y * f01.y;
            acc.z += e[u].y * f23.x;
            acc.w += e[u].y * f23.y;
        }

        if (haveNext) {
#pragma unroll
            for (int u = 0; u < 8; u++) e[u] = en[u];
        }
        j = jn;
        have = haveNext;
    }
    // serial tail (< 8 edges)
    for (; j < je; j++) {
        float2 et  = g_edge[j];
        uint2  hv = ((const uint2*)&g_h16[(size_t)__float_as_int(et.x) * HDIM])[lane];
        float2 f01 = __half22float2(*(__half2*)&hv.x);
        float2 f23 = __half22float2(*(__half2*)&hv.y);
        acc.x += et.y * f01.x;
        acc.y += et.y * f01.y;
        acc.z += et.y * f23.x;
        acc.w += et.y * f23.y;
    }

    if (sw == 1) s_part[nloc][lane] = acc;
    __syncthreads();

    if (sw == 0 && valid) {
        if (lane == 0) g_cnt[node] = 0;   // reset AFTER both warps consumed cnt

        float4 p = s_part[nloc][lane];
        acc.x += p.x; acc.y += p.y; acc.z += p.z; acc.w += p.w;

        float di = g_dinv[node];
        float swt = 2.0f * di * di;

        uint2  hh  = ((const uint2*)&g_h16[(size_t)node * HDIM])[lane];
        float2 h01 = __half22float2(*(__half2*)&hh.x);
        float2 h23 = __half22float2(*(__half2*)&hh.y);
        float4 hs4 = ((const float4*)&g_hs[(size_t)node * HDIM])[lane];
        float4 bc  = ((const float4*)bconv)[lane];
        float4 bs  = ((const float4*)bskip)[lane];

        float4 o;
        o.x = acc.x + swt * h01.x + bc.x + hs4.x + bs.x;
        o.y = acc.y + swt * h01.y + bc.y + hs4.y + bs.y;
        o.z = acc.z + swt * h23.x + bc.z + hs4.z + bs.z;
        o.w = acc.w + swt * h23.y + bc.w + hs4.w + bs.w;

        o.x = (o.x > 0.f) ? o.x : 0.1f * (__expf(o.x) - 1.0f);
        o.y = (o.y > 0.f) ? o.y : 0.1f * (__expf(o.y) - 1.0f);
        o.z = (o.z > 0.f) ? o.z : 0.1f * (__expf(o.z) - 1.0f);
        o.w = (o.w > 0.f) ? o.w : 0.1f * (__expf(o.w) - 1.0f);

        ((float4*)&out[(size_t)node * HDIM])[lane] = o;
    }
}

// ---------------------------------------------------------------- launch
// 5 launches: gemm (s2), degree, offsets, bucket, agg.
extern "C" void kernel_launch(void* const* d_in, const int* in_sizes, int n_in,
                              void* d_out, int out_size) {
    const float* x  = (const float*)d_in[0];
    const void*  ei = d_in[1];
    const float* Wc = (const float*)d_in[2];
    const float* bc = (const float*)d_in[3];
    const float* Ws = (const float*)d_in[4];
    const float* bs = (const float*)d_in[5];
    float* out = (float*)d_out;

    const int n = in_sizes[0] / HDIM;
    const int E = in_sizes[1] / 2;

    static cudaStream_t s2 = []() {
        cudaStream_t s; cudaStreamCreateWithFlags(&s, cudaStreamNonBlocking); return s;
    }();
    static cudaEvent_t ev_fork = []() {
        cudaEvent_t e; cudaEventCreateWithFlags(&e, cudaEventDisableTiming); return e;
    }();
    static cudaEvent_t ev_gemm = []() {
        cudaEvent_t e; cudaEventCreateWithFlags(&e, cudaEventDisableTiming); return e;
    }();
    static bool attr_done = []() {
        cudaFuncSetAttribute(k_gemm_mma,
                             cudaFuncAttributeMaxDynamicSharedMemorySize, SMEM_MMA);
        return true;
    }();
    (void)attr_done;

    // Fork: GEMM on s2, concurrent with edge preprocessing on the main stream.
    cudaEventRecord(ev_fork, 0);
    cudaStreamWaitEvent(s2, ev_fork, 0);
    k_gemm_mma<<<(n + 127) / 128, 512, SMEM_MMA, s2>>>(x, Wc, Ws, n);
    cudaEventRecord(ev_gemm, s2);

    k_degree <<<(E + 255) / 256, 256>>>(ei, E, n);
    k_offsets<<<(n + 255) / 256, 256>>>(n);
    k_bucket <<<(E + 255) / 256, 256>>>(ei, E, n);

    // Join: aggregation needs both the bucketed edges and g_h16/g_hs.
    cudaStreamWaitEvent(0, ev_gemm, 0);
    k_agg<<<(n + 3) / 4, 256>>>(bc, bs, out, n);
}

// round 17
// speedup vs baseline: 1.4206x; 1.2170x over previous
#include <cuda_runtime.h>
#include <cuda_fp16.h>
#include <cstdint>

#define NMAX 100000
#define EMAX 1600000
#define HDIM 128

// Scratch (static device globals — no runtime allocation).
__device__ __align__(16)  int    g_is64;                        // edge dtype flag
__device__                int    g_total;                       // bucket cursor base
__device__ __align__(128) int    g_cnt [NMAX];                  // incoming-edge count
__device__ __align__(128) int    g_off [NMAX];                  // bucket offsets
__device__ __align__(128) int    g_cur [NMAX];                  // bucket cursors
__device__ __align__(128) float  g_dinv[NMAX];                  // 1/sqrt(deg)
__device__ __align__(128) float2 g_edge[EMAX];                  // {src bits, norm} dst-bucketed
__device__ __align__(256) __half g_h16 [(size_t)NMAX * HDIM];   // x @ W_conv (fp16)
__device__ __align__(256) float  g_hs  [(size_t)NMAX * HDIM];   // x @ W_skip (fp32)

__device__ __forceinline__ void decode_edge(const void* __restrict__ ei, int E,
                                            int n, int e, int& src, int& dst) {
    if (g_is64) {
        src = (int)((const long long*)ei)[e];
        dst = (int)((const long long*)ei)[(size_t)E + e];
    } else {
        src = ((const int*)ei)[e];
        dst = ((const int*)ei)[(size_t)E + e];
    }
    src = min(max(src, 0), n - 1);
    dst = min(max(dst, 0), n - 1);
}

// ---------------------------------------------------------------- init (+ dtype detect)
__global__ void k_init(const int* __restrict__ ei32, int n) {
    int i = blockIdx.x * blockDim.x + threadIdx.x;
    if (i == 0) {
        int ornz = 0;
        for (int k = 0; k < 64; k++) ornz |= ei32[2 * k + 1];
        g_is64 = (ornz == 0) ? 1 : 0;
        g_total = 0;
    }
    if (i < n) g_cnt[i] = 0;
}

// ---------------------------------------------------------------- degree histogram
__global__ void k_degree(const void* __restrict__ ei, int E, int n) {
    int e = blockIdx.x * blockDim.x + threadIdx.x;
    if (e >= E) return;
    int src, dst;
    decode_edge(ei, E, n, e, src, dst);
    atomicAdd(&g_cnt[dst], 1);
}

// ---------------------------------------------------------------- offsets (scan-free) + dinv
__global__ void k_offsets(int n) {
    __shared__ int wsum[8];
    __shared__ int bbase;
    int i    = blockIdx.x * 256 + threadIdx.x;
    int lane = threadIdx.x & 31;
    int wid  = threadIdx.x >> 5;

    int c = (i < n) ? g_cnt[i] : 0;
    int v = c;
#pragma unroll
    for (int o = 1; o < 32; o <<= 1) {
        int t = __shfl_up_sync(0xffffffffu, v, o);
        if (lane >= o) v += t;
    }
    if (lane == 31) wsum[wid] = v;
    __syncthreads();
    if (threadIdx.x == 0) {
        int run = 0;
#pragma unroll
        for (int w = 0; w < 8; w++) { int t = wsum[w]; wsum[w] = run; run += t; }
        bbase = atomicAdd(&g_total, run);
    }
    __syncthreads();
    if (i < n) {
        int excl = bbase + wsum[wid] + v - c;
        g_off[i] = excl;
        g_cur[i] = excl;
        g_dinv[i] = rsqrtf((float)c + 2.0f);   // improved=True: +2 self-loop
    }
}

// ---------------------------------------------------------------- bucket (counting sort by dst)
__global__ void k_bucket(const void* __restrict__ ei, int E, int n) {
    int e = blockIdx.x * blockDim.x + threadIdx.x;
    if (e >= E) return;
    int src, dst;
    decode_edge(ei, E, n, e, src, dst);
    float nrm = g_dinv[src] * g_dinv[dst];
    int pos = atomicAdd(&g_cur[dst], 1);
    g_edge[pos] = make_float2(__int_as_float(src), nrm);
}

// ---------------------------------------------------------------- HMMA dual GEMM
// mma.sync m16n8k16 fp16 (base ISA). Split precision:
//   D = x_hi·W_hi + x_lo·W_hi + x_hi·W_lo   (lo·lo term ~2^-22, dropped)
#define SA_STR 40
#define SB_STR 40
#define SA_HALVES (128 * SA_STR)            // per hi/lo tile
#define SB_HALVES (256 * SB_STR)
#define SMEM_MMA ((2 * SA_HALVES + 2 * SB_HALVES) * 2)   // 61440 bytes

__device__ __forceinline__ void mma16816(float* d, const uint32_t* a,
                                         uint32_t b0, uint32_t b1) {
    asm volatile(
        "mma.sync.aligned.m16n8k16.row.col.f32.f16.f16.f32 "
        "{%0,%1,%2,%3}, {%4,%5,%6,%7}, {%8,%9}, {%0,%1,%2,%3};"
        : "+f"(d[0]), "+f"(d[1]), "+f"(d[2]), "+f"(d[3])
        : "r"(a[0]), "r"(a[1]), "r"(a[2]), "r"(a[3]), "r"(b0), "r"(b1));
}

__device__ __forceinline__ uint32_t pack_half2(float a, float b) {
    __half2 h = __floats2half2_rn(a, b);
    return *(uint32_t*)&h;
}

__global__ __launch_bounds__(512) void k_gemm_mma(const float* __restrict__ x,
                                                  const float* __restrict__ Wc,
                                                  const float* __restrict__ Ws,
                                                  int n) {
    extern __shared__ __align__(16) __half smem[];
    __half* sAhi = smem;
    __half* sAlo = sAhi + SA_HALVES;
    __half* sBhi = sAlo + SA_HALVES;
    __half* sBlo = sBhi + SB_HALVES;

    const int tid  = threadIdx.x;
    const int wid  = tid >> 5;
    const int lane = tid & 31;
    const int g    = lane >> 2;     // group id (0..7)
    const int tg   = lane & 3;      // thread in group
    const int mw   = (wid & 3) * 32;    // warp M offset (rows)
    const int nw   = (wid >> 2) * 64;   // warp N offset (cols of 256)
    const int node0 = blockIdx.x * 128;

    float d[2][8][4];
#pragma unroll
    for (int mi = 0; mi < 2; mi++)
#pragma unroll
        for (int ni = 0; ni < 8; ni++)
#pragma unroll
            for (int q = 0; q < 4; q++) d[mi][ni][q] = 0.f;

    for (int kc = 0; kc < 4; kc++) {
        // ---- load + split x chunk: 128 rows x 32 k (1024 float4, 2/thread)
#pragma unroll
        for (int i = 0; i < 2; i++) {
            int f4  = i * 512 + tid;
            int row = f4 >> 3;
            int k4  = f4 & 7;
            int node = node0 + row;
            float4 v = make_float4(0.f, 0.f, 0.f, 0.f);
            if (node < n) v = ((const float4*)x)[(size_t)node * 32 + kc * 8 + k4];
            float hx = __half2float(__float2half_rn(v.x));
            float hy = __half2float(__float2half_rn(v.y));
            float hz = __half2float(__float2half_rn(v.z));
            float hw = __half2float(__float2half_rn(v.w));
            int base = row * SA_STR + k4 * 4;
            *(uint32_t*)&sAhi[base]     = pack_half2(hx, hy);
            *(uint32_t*)&sAhi[base + 2] = pack_half2(hz, hw);
            *(uint32_t*)&sAlo[base]     = pack_half2(v.x - hx, v.y - hy);
            *(uint32_t*)&sAlo[base + 2] = pack_half2(v.z - hz, v.w - hw);
        }
        // ---- load + split W chunk: 32 k x 256 cols (8192 elems, 16/thread)
#pragma unroll
        for (int i = 0; i < 16; i++) {
            int f    = i * 512 + tid;
            int k    = f >> 8;
            int ncol = f & 255;
            int krow = kc * 32 + k;
            float v = (ncol < 128) ? Wc[krow * 128 + ncol]
                                   : Ws[krow * 128 + (ncol - 128)];
            __half hi = __float2half_rn(v);
            sBhi[ncol * SB_STR + k] = hi;
            sBlo[ncol * SB_STR + k] = __float2half_rn(v - __half2float(hi));
        }
        __syncthreads();

        // ---- 3 split passes x 2 k16 steps
#pragma unroll
        for (int p = 0; p < 3; p++) {
            const __half* A = (p == 1) ? sAlo : sAhi;
            const __half* B = (p == 2) ? sBlo : sBhi;
#pragma unroll
            for (int kk = 0; kk < 32; kk += 16) {
                uint32_t a[2][4];
#pragma unroll
                for (int mi = 0; mi < 2; mi++) {
                    int r0 = (mw + mi * 16 + g) * SA_STR + kk + tg * 2;
                    int r1 = r0 + 8 * SA_STR;
                    a[mi][0] = *(const uint32_t*)(A + r0);
                    a[mi][1] = *(const uint32_t*)(A + r1);
                    a[mi][2] = *(const uint32_t*)(A + r0 + 8);
                    a[mi][3] = *(const uint32_t*)(A + r1 + 8);
                }
#pragma unroll
                for (int ni = 0; ni < 8; ni++) {
                    int nb = (nw + ni * 8 + g) * SB_STR + kk + tg * 2;
                    uint32_t b0 = *(const uint32_t*)(B + nb);
                    uint32_t b1 = *(const uint32_t*)(B + nb + 8);
                    mma16816(d[0][ni], a[0], b0, b1);
                    mma16816(d[1][ni], a[1], b0, b1);
                }
            }
        }
        __syncthreads();
    }

    // ---- epilogue: conv half -> fp16 only; skip half -> fp32
#pragma unroll
    for (int mi = 0; mi < 2; mi++) {
#pragma unroll
        for (int hr = 0; hr < 2; hr++) {
            int node = node0 + mw + mi * 16 + g + hr * 8;
            if (node >= n) continue;
#pragma unroll
            for (int ni = 0; ni < 8; ni++) {
                int col = nw + ni * 8 + tg * 2;
                float v0 = d[mi][ni][hr * 2 + 0];
                float v1 = d[mi][ni][hr * 2 + 1];
                if (col < 128) {
                    *(uint32_t*)&g_h16[(size_t)node * HDIM + col] = pack_half2(v0, v1);
                } else {
                    *(float2*)&g_hs[(size_t)node * HDIM + (col - 128)] =
                        make_float2(v0, v1);
                }
            }
        }
    }
}

// ---------------------------------------------------------------- fused aggregation + epilogue
// TWO warps per node (R13 structure). NEW: each warp hoists ALL its edge
// metadata into shared memory with one lane-parallel coalesced load round,
// then the gather loop reads meta via LDS (29 cyc) instead of LDG (250 cyc)
// — the dependent chain per batch drops ~500 -> ~280 cyc with FEWER loop
// instructions and no extra live registers.
__global__ __launch_bounds__(256) void k_agg(const float* __restrict__ bconv,
                                             const float* __restrict__ bskip,
                                             float* __restrict__ out, int n) {
    __shared__ float2 s_meta[8][64];    // 4 KB: per-warp metadata slab
    __shared__ float4 s_part[4][32];
    const int tid  = threadIdx.x;
    const int lane = tid & 31;
    const int wid  = tid >> 5;
    const int nloc = wid >> 1;          // node slot in block (0..3)
    const int sw   = wid & 1;           // sub-warp of the pair
    const int node = blockIdx.x * 4 + nloc;
    const bool valid = (node < n);

    int beg = 0, cnt = 0;
    if (valid) { beg = g_off[node]; cnt = g_cnt[node]; }
    const int half = cnt >> 1;
    const int jb = sw ? (beg + half) : beg;
    const int je = sw ? (beg + cnt)  : (beg + half);
    const int m  = je - jb;             // this warp's edge count (≈8 avg)
    const int mc = min(m, 64);

    // hoist metadata: lane-parallel, 1-2 coalesced rounds
    for (int b = lane; b < mc; b += 32) s_meta[wid][b] = g_edge[jb + b];
    __syncwarp();

    float4 acc = make_float4(0.f, 0.f, 0.f, 0.f);
    int j = 0;
    for (; j + 8 <= mc; j += 8) {
        float2 e[8];
        uint2  h[8];
#pragma unroll
        for (int u = 0; u < 8; u++) e[u] = s_meta[wid][j + u];   // LDS, cheap
#pragma unroll
        for (int u = 0; u < 8; u++)
            h[u] = ((const uint2*)&g_h16[(size_t)__float_as_int(e[u].x) * HDIM])[lane];
#pragma unroll
        for (int u = 0; u < 8; u++) {
            float2 f01 = __half22float2(*(__half2*)&h[u].x);
            float2 f23 = __half22float2(*(__half2*)&h[u].y);
            acc.x += e[u].y * f01.x;
            acc.y += e[u].y * f01.y;
            acc.z += e[u].y * f23.x;
            acc.w += e[u].y * f23.y;
        }
    }
    for (; j < mc; j++) {                // tail: LDS meta -> single gather
        float2 e  = s_meta[wid][j];
        uint2  hv = ((const uint2*)&g_h16[(size_t)__float_as_int(e.x) * HDIM])[lane];
        float2 f01 = __half22float2(*(__half2*)&hv.x);
        float2 f23 = __half22float2(*(__half2*)&hv.y);
        acc.x += e.y * f01.x;
        acc.y += e.y * f01.y;
        acc.z += e.y * f23.x;
        acc.w += e.y * f23.y;
    }
    for (int jj = jb + mc; jj < je; jj++) {   // overflow (>64/warp: ~never)
        float2 e  = g_edge[jj];
        uint2  hv = ((const uint2*)&g_h16[(size_t)__float_as_int(e.x) * HDIM])[lane];
        float2 f01 = __half22float2(*(__half2*)&hv.x);
        float2 f23 = __half22float2(*(__half2*)&hv.y);
        acc.x += e.y * f01.x;
        acc.y += e.y * f01.y;
        acc.z += e.y * f23.x;
        acc.w += e.y * f23.y;
    }

    if (sw == 1) s_part[nloc][lane] = acc;
    __syncthreads();

    if (sw == 0 && valid) {
        float4 p = s_part[nloc][lane];
        acc.x += p.x; acc.y += p.y; acc.z += p.z; acc.w += p.w;

        float di = g_dinv[node];
        float swt = 2.0f * di * di;

        uint2  hh  = ((const uint2*)&g_h16[(size_t)node * HDIM])[lane];
        float2 h01 = __half22float2(*(__half2*)&hh.x);
        float2 h23 = __half22float2(*(__half2*)&hh.y);
        float4 hs4 = ((const float4*)&g_hs[(size_t)node * HDIM])[lane];
        float4 bc  = ((const float4*)bconv)[lane];
        float4 bs  = ((const float4*)bskip)[lane];

        float4 o;
        o.x = acc.x + swt * h01.x + bc.x + hs4.x + bs.x;
        o.y = acc.y + swt * h01.y + bc.y + hs4.y + bs.y;
        o.z = acc.z + swt * h23.x + bc.z + hs4.z + bs.z;
        o.w = acc.w + swt * h23.y + bc.w + hs4.w + bs.w;

        o.x = (o.x > 0.f) ? o.x : 0.1f * (__expf(o.x) - 1.0f);
        o.y = (o.y > 0.f) ? o.y : 0.1f * (__expf(o.y) - 1.0f);
        o.z = (o.z > 0.f) ? o.z : 0.1f * (__expf(o.z) - 1.0f);
        o.w = (o.w > 0.f) ? o.w : 0.1f * (__expf(o.w) - 1.0f);

        ((float4*)&out[(size_t)node * HDIM])[lane] = o;
    }
}

// ---------------------------------------------------------------- launch
extern "C" void kernel_launch(void* const* d_in, const int* in_sizes, int n_in,
                              void* d_out, int out_size) {
    const float* x  = (const float*)d_in[0];
    const void*  ei = d_in[1];
    const float* Wc = (const float*)d_in[2];
    const float* bc = (const float*)d_in[3];
    const float* Ws = (const float*)d_in[4];
    const float* bs = (const float*)d_in[5];
    float* out = (float*)d_out;

    const int n = in_sizes[0] / HDIM;
    const int E = in_sizes[1] / 2;

    static cudaStream_t s2 = []() {
        cudaStream_t s; cudaStreamCreateWithFlags(&s, cudaStreamNonBlocking); return s;
    }();
    static cudaEvent_t ev_fork = []() {
        cudaEvent_t e; cudaEventCreateWithFlags(&e, cudaEventDisableTiming); return e;
    }();
    static cudaEvent_t ev_gemm = []() {
        cudaEvent_t e; cudaEventCreateWithFlags(&e, cudaEventDisableTiming); return e;
    }();
    static bool attr_done = []() {
        cudaFuncSetAttribute(k_gemm_mma,
                             cudaFuncAttributeMaxDynamicSharedMemorySize, SMEM_MMA);
        return true;
    }();
    (void)attr_done;

    // Fork: GEMM on s2, concurrent with edge preprocessing on the main stream.
    cudaEventRecord(ev_fork, 0);
    cudaStreamWaitEvent(s2, ev_fork, 0);
    k_gemm_mma<<<(n + 127) / 128, 512, SMEM_MMA, s2>>>(x, Wc, Ws, n);
    cudaEventRecord(ev_gemm, s2);

    k_init   <<<(n + 255) / 256, 256>>>((const int*)ei, n);
    k_degree <<<(E + 255) / 256, 256>>>(ei, E, n);
    k_offsets<<<(n + 255) / 256, 256>>>(n);
    k_bucket <<<(E + 255) / 256, 256>>>(ei, E, n);

    // Join: aggregation needs both the bucketed edges and g_h16/g_hs.
    cudaStreamWaitEvent(0, ev_gemm, 0);
    k_agg<<<(n + 3) / 4, 256>>>(bc, bs, out, n);
}